// round 13
// baseline (speedup 1.0000x reference)
#include <cuda_runtime.h>
#include <cuda_bf16.h>
#include <cstdint>

#define BATCH   2
#define SEQLEN  2048
#define DMODEL  1024
#define DSTATE  16
#define DTRANK  64
#define NROWS   (BATCH * SEQLEN)          // 4096
#define NCHUNK  64
#define CLEN    (SEQLEN / NCHUNK)         // 32
#define NCH     (BATCH * DMODEL)          // 2048
#define NGRP    (NCH * NCHUNK)            // 131072
#define KSPLIT  8
#define SCAN_GRID 512

typedef unsigned long long ull;

// ---------------------------------------------------------------------------
// f32x2 packed-math helpers
// ---------------------------------------------------------------------------
__device__ __forceinline__ ull pack2(float lo, float hi) {
    ull r; asm("mov.b64 %0, {%1, %2};" : "=l"(r) : "f"(lo), "f"(hi)); return r;
}
__device__ __forceinline__ void unpack2(ull v, float& lo, float& hi) {
    asm("mov.b64 {%0, %1}, %2;" : "=f"(lo), "=f"(hi) : "l"(v));
}
__device__ __forceinline__ ull fma2(ull a, ull b, ull c) {
    ull d; asm("fma.rn.f32x2 %0, %1, %2, %3;" : "=l"(d) : "l"(a), "l"(b), "l"(c)); return d;
}
__device__ __forceinline__ ull mul2(ull a, ull b) {
    ull d; asm("mul.rn.f32x2 %0, %1, %2;" : "=l"(d) : "l"(a), "l"(b)); return d;
}

// ---------------------------------------------------------------------------
// Device scratch.  Boundary-state arrays are CHUNK-MAJOR: [chunk][ch][n]
// ---------------------------------------------------------------------------
__device__ float  g_dpp[(size_t)KSPLIT * NROWS * DTRANK];
__device__ float  g_bcp[(size_t)KSPLIT * NROWS * 32];
__device__ float  g_bp [(size_t)NROWS * DSTATE];
__device__ float  g_cp [(size_t)NROWS * DSTATE];
__device__ float2 g_dd [(size_t)NROWS * DMODEL];
__device__ float  g_hl [(size_t)NGRP * DSTATE];
__device__ float  g_T  [(size_t)NGRP];
__device__ float  g_hin[(size_t)NGRP * DSTATE];
__device__ unsigned g_barcnt  = 0;
__device__ unsigned g_barflag = 0;

// ---------------------------------------------------------------------------
// K1: split-K GEMM1 partials.  BM=64, BN=96, K=128/split, 256 thr, 4x6 f32x2.
//   As stored ROW-MAJOR with STS.128 (conflict-free); grid (64, 8).
// ---------------------------------------------------------------------------
__global__ __launch_bounds__(256)
void gemm1_kernel(const float* __restrict__ x,
                  const float* __restrict__ W,
                  const float* __restrict__ te)
{
    __shared__ float As[64][68];    // [row][k]  (row-major!)
    __shared__ float Ws[64][98];    // [k][col]
    __shared__ float ssg[128];

    const int tid  = threadIdx.x;
    const int row0 = blockIdx.x * 64;
    const int ks   = blockIdx.y;            // 0..7, K slice of 128
    const int ty   = tid >> 4;
    const int tx   = tid & 15;

    if (tid < 128)
        ssg[tid] = 1.f / (1.f + __expf(-te[ks * 128 + tid]));
    __syncthreads();

    ull accp[4][3];
#pragma unroll
    for (int i = 0; i < 4; i++)
#pragma unroll
        for (int j = 0; j < 3; j++) accp[i][j] = 0ull;

    for (int kk = 0; kk < 128; kk += 64) {
        const int kt = ks * 128 + kk;
        // A tile: 64 rows x 64 k, row-major, one STS.128 per float4
#pragma unroll
        for (int i = 0; i < 4; i++) {
            int e  = i * 256 + tid;
            int r  = e >> 4;
            int k4 = e & 15;
            float4 v = *(const float4*)&x[(size_t)(row0 + r) * DMODEL + kt + k4 * 4];
            *(float4*)&As[r][k4 * 4] = v;
        }
        // W tile: 96 cols x 64 k, k-major, sig folded at load
#pragma unroll
        for (int i = 0; i < 6; i++) {
            int e  = i * 256 + tid;
            int c  = e >> 4;
            int k4 = e & 15;
            float4 v = *(const float4*)&W[(size_t)c * DMODEL + kt + k4 * 4];
            Ws[k4 * 4 + 0][c] = v.x * ssg[kk + k4 * 4 + 0];
            Ws[k4 * 4 + 1][c] = v.y * ssg[kk + k4 * 4 + 1];
            Ws[k4 * 4 + 2][c] = v.z * ssg[kk + k4 * 4 + 2];
            Ws[k4 * 4 + 3][c] = v.w * ssg[kk + k4 * 4 + 3];
        }
        __syncthreads();

#pragma unroll 8
        for (int k = 0; k < 64; k++) {
            float a0 = As[ty * 4 + 0][k];
            float a1 = As[ty * 4 + 1][k];
            float a2 = As[ty * 4 + 2][k];
            float a3 = As[ty * 4 + 3][k];
            ull ap[4];
            ap[0] = pack2(a0, a0);
            ap[1] = pack2(a1, a1);
            ap[2] = pack2(a2, a2);
            ap[3] = pack2(a3, a3);
            ull wp0 = *(const ull*)&Ws[k][tx * 6 + 0];
            ull wp1 = *(const ull*)&Ws[k][tx * 6 + 2];
            ull wp2 = *(const ull*)&Ws[k][tx * 6 + 4];
#pragma unroll
            for (int i = 0; i < 4; i++) {
                accp[i][0] = fma2(ap[i], wp0, accp[i][0]);
                accp[i][1] = fma2(ap[i], wp1, accp[i][1]);
                accp[i][2] = fma2(ap[i], wp2, accp[i][2]);
            }
        }
        __syncthreads();
    }

#pragma unroll
    for (int i = 0; i < 4; i++) {
        int r = row0 + ty * 4 + i;
#pragma unroll
        for (int jp = 0; jp < 3; jp++) {
            float v0, v1;
            unpack2(accp[i][jp], v0, v1);
            int c = tx * 6 + jp * 2;
#pragma unroll
            for (int h = 0; h < 2; h++) {
                float v = h ? v1 : v0;
                int cc = c + h;
                if (cc < DTRANK)
                    g_dpp[((size_t)ks * NROWS + r) * DTRANK + cc] = v;
                else
                    g_bcp[((size_t)ks * NROWS + r) * 32 + (cc - DTRANK)] = v;
            }
        }
    }
}

// ---------------------------------------------------------------------------
// K2 (fused GEMM2 + chunk-local scan), chunk-major state output.
//   dps stored ROW-MAJOR with STS.128 (conflict-free).
// ---------------------------------------------------------------------------
__global__ __launch_bounds__(256)
void gemm2s_kernel(const float* __restrict__ x,
                   const float* __restrict__ dtw,
                   const float* __restrict__ dtb,
                   const float* __restrict__ te,
                   const float* __restrict__ A_log)
{
    __shared__ __align__(16) char smraw[45568];
    float  (*dps)[68]  = (float (*)[68]) (smraw);                // 32x68 = 8704 B
    float  (*ws)[132]  = (float (*)[132])(smraw + 8704);         // 33792 B
    float2 (*sdd)[132] = (float2(*)[132])(smraw + 8704);         // union w/ ws
    float  (*Bs)[16]   = (float (*)[16]) (smraw + 42496);        // 2048 B
    float*  ssg        = (float*)(smraw + 44544);                // 512 B
    float*  sdtb       = (float*)(smraw + 45056);                // 512 B

    const int tid  = threadIdx.x;
    const int row0 = blockIdx.x * 32;
    const int by   = blockIdx.y;
    const int ty   = tid >> 4;
    const int tx   = tid & 15;

    if (tid < 128) {
        float tev = te[by * 128 + tid];
        ssg[tid]  = 1.f / (1.f + __expf(-tev));
        sdtb[tid] = dtb[by * 128 + tid];
    }

    // ---- Phase A: sum partials (dps row-major, STS.128) ----
#pragma unroll
    for (int i = 0; i < 2; i++) {
        int e  = i * 256 + tid;
        int r  = e >> 4;
        int k4 = e & 15;
        float4 s = make_float4(0.f, 0.f, 0.f, 0.f);
#pragma unroll
        for (int ks = 0; ks < KSPLIT; ks++) {
            float4 v = *(const float4*)&g_dpp[((size_t)ks * NROWS + row0 + r) * DTRANK + k4 * 4];
            s.x += v.x; s.y += v.y; s.z += v.z; s.w += v.w;
        }
        *(float4*)&dps[r][k4 * 4] = s;
    }
    {
        int r  = tid >> 3;
        int c4 = tid & 7;
        float4 s = make_float4(0.f, 0.f, 0.f, 0.f);
#pragma unroll
        for (int ks = 0; ks < KSPLIT; ks++) {
            float4 v = *(const float4*)&g_bcp[((size_t)ks * NROWS + row0 + r) * 32 + c4 * 4];
            s.x += v.x; s.y += v.y; s.z += v.z; s.w += v.w;
        }
        if (c4 < 4) {
            *(float4*)&Bs[r][c4 * 4] = s;
            if (by == 0) *(float4*)&g_bp[(size_t)(row0 + r) * DSTATE + c4 * 4] = s;
        } else if (by == 0) {
            *(float4*)&g_cp[(size_t)(row0 + r) * DSTATE + (c4 - 4) * 4] = s;
        }
    }
#pragma unroll
    for (int i = 0; i < 8; i++) {
        int e  = i * 256 + tid;
        int c  = e >> 4;
        int k4 = e & 15;
        float4 v = *(const float4*)&dtw[(size_t)(by * 128 + c) * DTRANK + k4 * 4];
        ws[k4 * 4 + 0][c] = v.x;
        ws[k4 * 4 + 1][c] = v.y;
        ws[k4 * 4 + 2][c] = v.z;
        ws[k4 * 4 + 3][c] = v.w;
    }
    __syncthreads();

    // ---- Phase B: f32x2 GEMM ----
    ull accp[2][4];
#pragma unroll
    for (int i = 0; i < 2; i++)
#pragma unroll
        for (int j = 0; j < 4; j++) accp[i][j] = 0ull;

#pragma unroll 16
    for (int k = 0; k < 64; k++) {
        float a0 = dps[ty * 2 + 0][k];
        float a1 = dps[ty * 2 + 1][k];
        ull a0p = pack2(a0, a0);
        ull a1p = pack2(a1, a1);
        ulonglong2 w01 = *(const ulonglong2*)&ws[k][tx * 8];
        ulonglong2 w23 = *(const ulonglong2*)&ws[k][tx * 8 + 4];
        accp[0][0] = fma2(a0p, w01.x, accp[0][0]);
        accp[0][1] = fma2(a0p, w01.y, accp[0][1]);
        accp[0][2] = fma2(a0p, w23.x, accp[0][2]);
        accp[0][3] = fma2(a0p, w23.y, accp[0][3]);
        accp[1][0] = fma2(a1p, w01.x, accp[1][0]);
        accp[1][1] = fma2(a1p, w01.y, accp[1][1]);
        accp[1][2] = fma2(a1p, w23.x, accp[1][2]);
        accp[1][3] = fma2(a1p, w23.y, accp[1][3]);
    }
    __syncthreads();

    // ---- Phase C: epilogue ----
#pragma unroll
    for (int i = 0; i < 2; i++) {
        int lloc = ty * 2 + i;
        int r    = row0 + lloc;
        int c0   = by * 128 + tx * 8;
        float4 x0 = *(const float4*)&x[(size_t)r * DMODEL + c0];
        float4 x1 = *(const float4*)&x[(size_t)r * DMODEL + c0 + 4];
        float xv[8] = {x0.x, x0.y, x0.z, x0.w, x1.x, x1.y, x1.z, x1.w};
        float dl[8], du[8];
#pragma unroll
        for (int jp = 0; jp < 4; jp++) {
            float v0, v1;
            unpack2(accp[i][jp], v0, v1);
            float av[2] = {v0, v1};
#pragma unroll
            for (int h = 0; h < 2; h++) {
                int j = jp * 2 + h;
                int cl = tx * 8 + j;
                float u  = xv[j] * ssg[cl];
                float v  = av[h] + sdtb[cl];
                float delta = fmaxf(v, 0.f) + __logf(1.f + __expf(-fabsf(v)));
                dl[j] = delta;
                du[j] = delta * u;
            }
        }
        float4* dst = (float4*)&g_dd[(size_t)r * DMODEL + c0];
#pragma unroll
        for (int j = 0; j < 4; j++) {
            float4 pk = make_float4(dl[2*j], du[2*j], dl[2*j+1], du[2*j+1]);
            dst[j] = pk;
            *(float4*)&sdd[lloc][tx * 8 + j * 2] = pk;
        }
    }
    __syncthreads();

    // ---- Phase D: chunk-local scan (chunk-major output) ----
    {
        const int dloc = tid & 127;
        const int nh   = tid >> 7;
        const int b    = row0 >> 11;
        const int chunk= (row0 >> 5) & (NCHUNK - 1);
        const int d    = by * 128 + dloc;
        const size_t base = (size_t)chunk * NCH + b * DMODEL + d;

        float A[8];
#pragma unroll
        for (int j = 0; j < 8; j++) A[j] = -__expf(A_log[(size_t)d * DSTATE + nh * 8 + j]);
        bool uniform = true;
#pragma unroll
        for (int j = 1; j < 8; j++) uniform &= (A[j] == A[0]);

        ull hp[4] = {0ull, 0ull, 0ull, 0ull};
        float T = 0.f;

        if (uniform) {
            const float A0 = A[0];
#pragma unroll 4
            for (int l = 0; l < CLEN; l++) {
                float2 t = sdd[l][dloc];
                T += t.x;
                float a = __expf(t.x * A0);
                ull ap  = pack2(a, a);
                ull dup = pack2(t.y, t.y);
                ulonglong2 b01 = *(const ulonglong2*)&Bs[l][nh * 8];
                ulonglong2 b23 = *(const ulonglong2*)&Bs[l][nh * 8 + 4];
                hp[0] = fma2(ap, hp[0], mul2(dup, b01.x));
                hp[1] = fma2(ap, hp[1], mul2(dup, b01.y));
                hp[2] = fma2(ap, hp[2], mul2(dup, b23.x));
                hp[3] = fma2(ap, hp[3], mul2(dup, b23.y));
            }
        } else {
#pragma unroll 2
            for (int l = 0; l < CLEN; l++) {
                float2 t = sdd[l][dloc];
                T += t.x;
                ull dup = pack2(t.y, t.y);
                ulonglong2 b01 = *(const ulonglong2*)&Bs[l][nh * 8];
                ulonglong2 b23 = *(const ulonglong2*)&Bs[l][nh * 8 + 4];
                ull bb[4] = {b01.x, b01.y, b23.x, b23.y};
#pragma unroll
                for (int p = 0; p < 4; p++) {
                    ull ap = pack2(__expf(t.x * A[p*2]), __expf(t.x * A[p*2+1]));
                    hp[p] = fma2(ap, hp[p], mul2(dup, bb[p]));
                }
            }
        }
#pragma unroll
        for (int p = 0; p < 4; p++)
            *(ull*)&g_hl[base * DSTATE + nh * 8 + p * 2] = hp[p];
        if (nh == 0) g_T[base] = T;
    }
}

// ---------------------------------------------------------------------------
// K3 (fused pass B + pass C with device-wide spin barrier).
// ---------------------------------------------------------------------------
__global__ __launch_bounds__(256, 4)
void scanBC_kernel(const float* __restrict__ A_log,
                   const float* __restrict__ Dp,
                   float* __restrict__ out)
{
    __shared__ __align__(16) float sm[CLEN * DSTATE * 2];   // 4KB

    const int tid  = threadIdx.x;
    const unsigned gen0 = *(volatile unsigned*)&g_barflag;

    // ================= Phase B: boundary combine =================
    {
        const int idx = blockIdx.x * 256 + tid;
        const int ch  = idx >> 6;
        const int q   = (idx >> 4) & 3;
        const int n   = idx & 15;
        const int d   = ch & (DMODEL - 1);

        const float A = -__expf(A_log[(size_t)d * DSTATE + n]);

        float a[16], hl[16];
#pragma unroll
        for (int i = 0; i < 16; i++) {
            int c = q * 16 + i;
            hl[i] = g_hl[((size_t)c * NCH + ch) * DSTATE + n];
            a[i]  = g_T [(size_t)c * NCH + ch];
        }
#pragma unroll
        for (int i = 0; i < 16; i++) a[i] = __expf(a[i] * A);

        float Aa = 1.f, Bb = 0.f;
#pragma unroll
        for (int i = 0; i < 16; i++) {
            Bb = fmaf(a[i], Bb, hl[i]);
            Aa *= a[i];
        }
        const int chl = tid >> 6;
        float2* smq = (float2*)sm;
        smq[(chl * 4 + q) * 16 + n] = make_float2(Aa, Bb);
        __syncthreads();

        float hin = 0.f;
#pragma unroll
        for (int qq = 0; qq < 3; qq++) {
            if (qq < q) {
                float2 m = smq[(chl * 4 + qq) * 16 + n];
                hin = fmaf(m.x, hin, m.y);
            }
        }
#pragma unroll
        for (int i = 0; i < 16; i++) {
            int c = q * 16 + i;
            g_hin[((size_t)c * NCH + ch) * DSTATE + n] = hin;
            hin = fmaf(a[i], hin, hl[i]);
        }
    }

    // ================= device-wide barrier =================
    __threadfence();
    __syncthreads();
    if (tid == 0) {
        unsigned old = atomicAdd(&g_barcnt, 1u);
        if (old == gridDim.x - 1) {
            g_barcnt = 0;
            __threadfence();
            atomicAdd(&g_barflag, 1u);
        } else {
            while (*(volatile unsigned*)&g_barflag == gen0) { }
        }
    }
    __syncthreads();
    __threadfence();

    // ================= Phase C: full re-scan =================
    {
        float (*Bs)[DSTATE] = (float(*)[DSTATE])sm;
        float (*Cs)[DSTATE] = (float(*)[DSTATE])(sm + CLEN * DSTATE);

        const int blk   = blockIdx.x;
        const int b     = blk >> 8;
        const int rem   = blk & 255;
        const int dgrp  = rem >> 6;
        const int chunk = rem & 63;
        const int d     = dgrp * 256 + tid;
        const int ch    = b * DMODEL + d;
        const int l0    = chunk * CLEN;
        const size_t hbase = ((size_t)chunk * NCH + ch) * DSTATE;

        if (tid < CLEN * DSTATE / 4) {
            const float4* sb = (const float4*)&g_bp[((size_t)b * SEQLEN + l0) * DSTATE];
            ((float4*)Bs)[tid] = sb[tid];
        } else if (tid < CLEN * DSTATE / 2) {
            const float4* sc = (const float4*)&g_cp[((size_t)b * SEQLEN + l0) * DSTATE];
            ((float4*)Cs)[tid - CLEN * DSTATE / 4] = sc[tid - CLEN * DSTATE / 4];
        }

        float A[DSTATE];
#pragma unroll
        for (int n = 0; n < DSTATE; n++) A[n] = -__expf(A_log[(size_t)d * DSTATE + n]);
        bool uniform = true;
#pragma unroll
        for (int n = 1; n < DSTATE; n++) uniform &= (A[n] == A[0]);

        ull hp[8];
#pragma unroll
        for (int p = 0; p < 8; p++)
            hp[p] = *(const ull*)&g_hin[hbase + p * 2];

        const float Dpd = Dp[d];

        const float2* __restrict__ dd = g_dd + ((size_t)b * SEQLEN + l0) * DMODEL + d;
        float*        __restrict__ op = out  + ((size_t)b * SEQLEN + l0) * DMODEL + d;
        __syncthreads();

        if (uniform) {
            const float A0 = A[0];
            for (int lb = 0; lb < CLEN / 8; lb++) {
                float2 t[8];
#pragma unroll
                for (int i = 0; i < 8; i++) t[i] = dd[(size_t)(lb * 8 + i) * DMODEL];
                float av[8], u[8];
#pragma unroll
                for (int i = 0; i < 8; i++) {
                    av[i] = __expf(t[i].x * A0);
                    u[i]  = __fdividef(t[i].y, fmaxf(t[i].x, 1e-38f));
                }
#pragma unroll
                for (int i = 0; i < 8; i++) {
                    int l = lb * 8 + i;
                    ull ap  = pack2(av[i], av[i]);
                    ull dup = pack2(t[i].y, t[i].y);
                    ull yp  = 0ull;
                    const ulonglong2* bl = (const ulonglong2*)&Bs[l][0];
                    const ulonglong2* cl = (const ulonglong2*)&Cs[l][0];
#pragma unroll
                    for (int qd = 0; qd < 4; qd++) {
                        ulonglong2 bq = bl[qd];
                        ulonglong2 cq = cl[qd];
                        hp[2*qd+0] = fma2(ap, hp[2*qd+0], mul2(dup, bq.x));
                        yp         = fma2(hp[2*qd+0], cq.x, yp);
                        hp[2*qd+1] = fma2(ap, hp[2*qd+1], mul2(dup, bq.y));
                        yp         = fma2(hp[2*qd+1], cq.y, yp);
                    }
                    float ylo, yhi;
                    unpack2(yp, ylo, yhi);
                    op[(size_t)l * DMODEL] = fmaf(u[i], Dpd, ylo + yhi);
                }
            }
        } else {
            for (int lb = 0; lb < CLEN / 8; lb++) {
                float2 t[8];
#pragma unroll
                for (int i = 0; i < 8; i++) t[i] = dd[(size_t)(lb * 8 + i) * DMODEL];
                float u[8];
#pragma unroll
                for (int i = 0; i < 8; i++)
                    u[i] = __fdividef(t[i].y, fmaxf(t[i].x, 1e-38f));
#pragma unroll
                for (int i = 0; i < 8; i++) {
                    int l = lb * 8 + i;
                    ull dup = pack2(t[i].y, t[i].y);
                    ull yp  = 0ull;
                    const ulonglong2* bl = (const ulonglong2*)&Bs[l][0];
                    const ulonglong2* cl = (const ulonglong2*)&Cs[l][0];
#pragma unroll
                    for (int qd = 0; qd < 4; qd++) {
                        ulonglong2 bq = bl[qd];
                        ulonglong2 cq = cl[qd];
                        ull ap0 = pack2(__expf(t[i].x * A[4*qd+0]), __expf(t[i].x * A[4*qd+1]));
                        ull ap1 = pack2(__expf(t[i].x * A[4*qd+2]), __expf(t[i].x * A[4*qd+3]));
                        hp[2*qd+0] = fma2(ap0, hp[2*qd+0], mul2(dup, bq.x));
                        yp         = fma2(hp[2*qd+0], cq.x, yp);
                        hp[2*qd+1] = fma2(ap1, hp[2*qd+1], mul2(dup, bq.y));
                        yp         = fma2(hp[2*qd+1], cq.y, yp);
                    }
                    float ylo, yhi;
                    unpack2(yp, ylo, yhi);
                    op[(size_t)l * DMODEL] = fmaf(u[i], Dpd, ylo + yhi);
                }
            }
        }
    }
}

// ---------------------------------------------------------------------------
// Launch: 3 kernels total
// ---------------------------------------------------------------------------
extern "C" void kernel_launch(void* const* d_in, const int* in_sizes, int n_in,
                              void* d_out, int out_size)
{
    const float* x    = (const float*)d_in[0];
    const float* Alog = (const float*)d_in[1];
    const float* xpw  = (const float*)d_in[2];
    const float* dtw  = (const float*)d_in[3];
    const float* dtb  = (const float*)d_in[4];
    const float* Dp   = (const float*)d_in[5];
    const float* te   = (const float*)d_in[6];
    float* out = (float*)d_out;

    gemm1_kernel <<<dim3(NROWS / 64, KSPLIT), 256>>>(x, xpw, te);
    gemm2s_kernel<<<dim3(NROWS / 32, DMODEL / 128), 256>>>(x, dtw, dtb, te, Alog);
    scanBC_kernel<<<SCAN_GRID, 256>>>(Alog, Dp, out);
}

// round 17
// speedup vs baseline: 1.1057x; 1.1057x over previous
#include <cuda_runtime.h>
#include <cuda_bf16.h>
#include <mma.h>
#include <cstdint>

using namespace nvcuda;

#define BATCH   2
#define SEQLEN  2048
#define DMODEL  1024
#define DSTATE  16
#define DTRANK  64
#define NROWS   (BATCH * SEQLEN)          // 4096
#define NCHUNK  64
#define CLEN    (SEQLEN / NCHUNK)         // 32
#define NCH     (BATCH * DMODEL)          // 2048
#define NGRP    (NCH * NCHUNK)            // 131072
#define KSPLIT  8
#define SCAN_GRID 512

typedef unsigned long long ull;

// ---------------------------------------------------------------------------
// f32x2 packed-math helpers
// ---------------------------------------------------------------------------
__device__ __forceinline__ ull pack2(float lo, float hi) {
    ull r; asm("mov.b64 %0, {%1, %2};" : "=l"(r) : "f"(lo), "f"(hi)); return r;
}
__device__ __forceinline__ void unpack2(ull v, float& lo, float& hi) {
    asm("mov.b64 {%0, %1}, %2;" : "=f"(lo), "=f"(hi) : "l"(v));
}
__device__ __forceinline__ ull fma2(ull a, ull b, ull c) {
    ull d; asm("fma.rn.f32x2 %0, %1, %2, %3;" : "=l"(d) : "l"(a), "l"(b), "l"(c)); return d;
}
__device__ __forceinline__ ull mul2(ull a, ull b) {
    ull d; asm("mul.rn.f32x2 %0, %1, %2;" : "=l"(d) : "l"(a), "l"(b)); return d;
}

// ---------------------------------------------------------------------------
// Device scratch.  Boundary-state arrays are CHUNK-MAJOR: [chunk][ch][n]
// ---------------------------------------------------------------------------
__device__ __nv_bfloat16 g_xh[(size_t)NROWS * DMODEL];
__device__ __nv_bfloat16 g_xl[(size_t)NROWS * DMODEL];
__device__ __nv_bfloat16 g_wh[96 * DMODEL];
__device__ __nv_bfloat16 g_wl[96 * DMODEL];
__device__ float  g_dpp[(size_t)KSPLIT * NROWS * DTRANK];
__device__ float  g_bcp[(size_t)KSPLIT * NROWS * 32];
__device__ float  g_bp [(size_t)NROWS * DSTATE];
__device__ float  g_cp [(size_t)NROWS * DSTATE];
__device__ float2 g_dd [(size_t)NROWS * DMODEL];
__device__ float  g_hl [(size_t)NGRP * DSTATE];
__device__ float  g_T  [(size_t)NGRP];
__device__ float  g_hin[(size_t)NGRP * DSTATE];
__device__ unsigned g_barcnt  = 0;
__device__ unsigned g_barflag = 0;

// ---------------------------------------------------------------------------
// K0: split x and W*sig(te) into bf16 (hi, lo) pairs.
// ---------------------------------------------------------------------------
__global__ __launch_bounds__(256)
void prep_split_kernel(const float* __restrict__ x,
                       const float* __restrict__ W,
                       const float* __restrict__ te)
{
    const int tid = threadIdx.x;
    if (blockIdx.x < 4096) {
        size_t i4 = (size_t)blockIdx.x * 256 + tid;       // float4 index
        float4 v = *(const float4*)&x[i4 * 4];
        float vv[4] = {v.x, v.y, v.z, v.w};
        __nv_bfloat16 h[4], l[4];
#pragma unroll
        for (int j = 0; j < 4; j++) {
            h[j] = __float2bfloat16_rn(vv[j]);
            l[j] = __float2bfloat16_rn(vv[j] - __bfloat162float(h[j]));
        }
        *(ull*)&g_xh[i4 * 4] = *(ull*)h;
        *(ull*)&g_xl[i4 * 4] = *(ull*)l;
    } else {
        size_t i4 = (size_t)(blockIdx.x - 4096) * 256 + tid;
        if (i4 < 96 * DMODEL / 4) {
            float4 v = *(const float4*)&W[i4 * 4];
            int k0 = (int)((i4 * 4) & (DMODEL - 1));
            float vv[4] = {v.x, v.y, v.z, v.w};
            __nv_bfloat16 h[4], l[4];
#pragma unroll
            for (int j = 0; j < 4; j++) {
                float sg = 1.f / (1.f + __expf(-te[k0 + j]));
                float w  = vv[j] * sg;
                h[j] = __float2bfloat16_rn(w);
                l[j] = __float2bfloat16_rn(w - __bfloat162float(h[j]));
            }
            *(ull*)&g_wh[i4 * 4] = *(ull*)h;
            *(ull*)&g_wl[i4 * 4] = *(ull*)l;
        }
    }
}

// ---------------------------------------------------------------------------
// K1: wmma bf16 split-precision GEMM1.
//   grid (64 M-tiles, 8 K-splits).  CTA: M=64, N=96, K=128 (2 chunks of 64).
//   8 warps, 4x2 warp grid; each warp: 16 rows x 48 cols = 3 m16n16k16 accs.
//   D = Ah*Bh + Ah*Bl + Al*Bh  (f32 accumulate).
// ---------------------------------------------------------------------------
#define LDM_T   72                          // bf16 elements (64 + 8 pad)
#define SM_AH   0
#define SM_AL   (SM_AH + 64 * LDM_T * 2)    //  9216
#define SM_BH   (SM_AL + 64 * LDM_T * 2)    // 18432
#define SM_BL   (SM_BH + 96 * LDM_T * 2)    // 32256
#define SM_SZ   (SM_BL + 96 * LDM_T * 2)    // 46080
#define LDM_D   104                         // float elements

__global__ __launch_bounds__(256)
void gemm1_wmma_kernel()
{
    __shared__ __align__(16) char sm[SM_SZ];
    __nv_bfloat16* Ah = (__nv_bfloat16*)(sm + SM_AH);
    __nv_bfloat16* Al = (__nv_bfloat16*)(sm + SM_AL);
    __nv_bfloat16* Bh = (__nv_bfloat16*)(sm + SM_BH);
    __nv_bfloat16* Bl = (__nv_bfloat16*)(sm + SM_BL);
    float* Ds = (float*)sm;                 // union (used after MMA)

    const int tid  = threadIdx.x;
    const int wid  = tid >> 5;
    const int wm   = wid >> 1;              // 0..3 (M)
    const int wn   = wid & 1;               // 0..1 (N)
    const int mtile = blockIdx.x;           // 0..63
    const int ks    = blockIdx.y;           // 0..7
    const size_t row0 = (size_t)mtile * 64;

    wmma::fragment<wmma::accumulator, 16, 16, 16, float> acc[3];
#pragma unroll
    for (int t = 0; t < 3; t++) wmma::fill_fragment(acc[t], 0.f);

    for (int kc = 0; kc < 2; kc++) {
        const int kbase = ks * 128 + kc * 64;
        // load A chunk: 64 rows x 64 bf16 (hi & lo).  8 thr/row, 2 passes.
#pragma unroll
        for (int i = 0; i < 2; i++) {
            int e  = i * 256 + tid;
            int r  = e >> 3;
            int k8 = e & 7;
            size_t gi = (row0 + r) * DMODEL + kbase + k8 * 8;
            *(float4*)&Ah[r * LDM_T + k8 * 8] = *(const float4*)&g_xh[gi];
            *(float4*)&Al[r * LDM_T + k8 * 8] = *(const float4*)&g_xl[gi];
        }
        // load B chunk: 96 rows x 64 bf16 (hi & lo).
#pragma unroll
        for (int i = 0; i < 3; i++) {
            int e  = i * 256 + tid;
            int r  = e >> 3;
            int k8 = e & 7;
            size_t gi = (size_t)r * DMODEL + kbase + k8 * 8;
            *(float4*)&Bh[r * LDM_T + k8 * 8] = *(const float4*)&g_wh[gi];
            *(float4*)&Bl[r * LDM_T + k8 * 8] = *(const float4*)&g_wl[gi];
        }
        __syncthreads();

#pragma unroll
        for (int kf = 0; kf < 4; kf++) {
            wmma::fragment<wmma::matrix_a, 16, 16, 16, __nv_bfloat16, wmma::row_major> ah, al;
            wmma::load_matrix_sync(ah, Ah + wm * 16 * LDM_T + kf * 16, LDM_T);
            wmma::load_matrix_sync(al, Al + wm * 16 * LDM_T + kf * 16, LDM_T);
#pragma unroll
            for (int nt = 0; nt < 3; nt++) {
                int nrow = wn * 48 + nt * 16;
                wmma::fragment<wmma::matrix_b, 16, 16, 16, __nv_bfloat16, wmma::col_major> bh, bl;
                wmma::load_matrix_sync(bh, Bh + nrow * LDM_T + kf * 16, LDM_T);
                wmma::load_matrix_sync(bl, Bl + nrow * LDM_T + kf * 16, LDM_T);
                wmma::mma_sync(acc[nt], ah, bh, acc[nt]);
                wmma::mma_sync(acc[nt], ah, bl, acc[nt]);
                wmma::mma_sync(acc[nt], al, bh, acc[nt]);
            }
        }
        __syncthreads();
    }

    // stage D in smem (union with tiles; all MMA consumed)
#pragma unroll
    for (int nt = 0; nt < 3; nt++)
        wmma::store_matrix_sync(Ds + (wm * 16) * LDM_D + wn * 48 + nt * 16,
                                acc[nt], LDM_D, wmma::mem_row_major);
    __syncthreads();

    // scatter: 64 rows x 24 float4 (96 floats) -> dpp (16 f4) | bcp (8 f4)
#pragma unroll
    for (int i = 0; i < 6; i++) {
        int e = i * 256 + tid;      // 0..1535
        int r = e / 24;
        int q = e - r * 24;
        float4 v = *(const float4*)&Ds[r * LDM_D + q * 4];
        size_t gr = (size_t)ks * NROWS + row0 + r;
        if (q < 16) *(float4*)&g_dpp[gr * DTRANK + q * 4] = v;
        else        *(float4*)&g_bcp[gr * 32 + (q - 16) * 4] = v;
    }
}

// ---------------------------------------------------------------------------
// K2 (fused GEMM2 + chunk-local scan), chunk-major state output.
// ---------------------------------------------------------------------------
__global__ __launch_bounds__(256)
void gemm2s_kernel(const float* __restrict__ x,
                   const float* __restrict__ dtw,
                   const float* __restrict__ dtb,
                   const float* __restrict__ te,
                   const float* __restrict__ A_log)
{
    __shared__ __align__(16) char smraw[45568];
    float  (*dps)[68]  = (float (*)[68]) (smraw);
    float  (*ws)[132]  = (float (*)[132])(smraw + 8704);
    float2 (*sdd)[132] = (float2(*)[132])(smraw + 8704);
    float  (*Bs)[16]   = (float (*)[16]) (smraw + 42496);
    float*  ssg        = (float*)(smraw + 44544);
    float*  sdtb       = (float*)(smraw + 45056);

    const int tid  = threadIdx.x;
    const int row0 = blockIdx.x * 32;
    const int by   = blockIdx.y;
    const int ty   = tid >> 4;
    const int tx   = tid & 15;

    if (tid < 128) {
        float tev = te[by * 128 + tid];
        ssg[tid]  = 1.f / (1.f + __expf(-tev));
        sdtb[tid] = dtb[by * 128 + tid];
    }

#pragma unroll
    for (int i = 0; i < 2; i++) {
        int e  = i * 256 + tid;
        int r  = e >> 4;
        int k4 = e & 15;
        float4 s = make_float4(0.f, 0.f, 0.f, 0.f);
#pragma unroll
        for (int ks = 0; ks < KSPLIT; ks++) {
            float4 v = *(const float4*)&g_dpp[((size_t)ks * NROWS + row0 + r) * DTRANK + k4 * 4];
            s.x += v.x; s.y += v.y; s.z += v.z; s.w += v.w;
        }
        *(float4*)&dps[r][k4 * 4] = s;
    }
    {
        int r  = tid >> 3;
        int c4 = tid & 7;
        float4 s = make_float4(0.f, 0.f, 0.f, 0.f);
#pragma unroll
        for (int ks = 0; ks < KSPLIT; ks++) {
            float4 v = *(const float4*)&g_bcp[((size_t)ks * NROWS + row0 + r) * 32 + c4 * 4];
            s.x += v.x; s.y += v.y; s.z += v.z; s.w += v.w;
        }
        if (c4 < 4) {
            *(float4*)&Bs[r][c4 * 4] = s;
            if (by == 0) *(float4*)&g_bp[(size_t)(row0 + r) * DSTATE + c4 * 4] = s;
        } else if (by == 0) {
            *(float4*)&g_cp[(size_t)(row0 + r) * DSTATE + (c4 - 4) * 4] = s;
        }
    }
#pragma unroll
    for (int i = 0; i < 8; i++) {
        int e  = i * 256 + tid;
        int c  = e >> 4;
        int k4 = e & 15;
        float4 v = *(const float4*)&dtw[(size_t)(by * 128 + c) * DTRANK + k4 * 4];
        ws[k4 * 4 + 0][c] = v.x;
        ws[k4 * 4 + 1][c] = v.y;
        ws[k4 * 4 + 2][c] = v.z;
        ws[k4 * 4 + 3][c] = v.w;
    }
    __syncthreads();

    ull accp[2][4];
#pragma unroll
    for (int i = 0; i < 2; i++)
#pragma unroll
        for (int j = 0; j < 4; j++) accp[i][j] = 0ull;

#pragma unroll 16
    for (int k = 0; k < 64; k++) {
        float a0 = dps[ty * 2 + 0][k];
        float a1 = dps[ty * 2 + 1][k];
        ull a0p = pack2(a0, a0);
        ull a1p = pack2(a1, a1);
        ulonglong2 w01 = *(const ulonglong2*)&ws[k][tx * 8];
        ulonglong2 w23 = *(const ulonglong2*)&ws[k][tx * 8 + 4];
        accp[0][0] = fma2(a0p, w01.x, accp[0][0]);
        accp[0][1] = fma2(a0p, w01.y, accp[0][1]);
        accp[0][2] = fma2(a0p, w23.x, accp[0][2]);
        accp[0][3] = fma2(a0p, w23.y, accp[0][3]);
        accp[1][0] = fma2(a1p, w01.x, accp[1][0]);
        accp[1][1] = fma2(a1p, w01.y, accp[1][1]);
        accp[1][2] = fma2(a1p, w23.x, accp[1][2]);
        accp[1][3] = fma2(a1p, w23.y, accp[1][3]);
    }
    __syncthreads();

#pragma unroll
    for (int i = 0; i < 2; i++) {
        int lloc = ty * 2 + i;
        int r    = row0 + lloc;
        int c0   = by * 128 + tx * 8;
        float4 x0 = *(const float4*)&x[(size_t)r * DMODEL + c0];
        float4 x1 = *(const float4*)&x[(size_t)r * DMODEL + c0 + 4];
        float xv[8] = {x0.x, x0.y, x0.z, x0.w, x1.x, x1.y, x1.z, x1.w};
        float dl[8], du[8];
#pragma unroll
        for (int jp = 0; jp < 4; jp++) {
            float v0, v1;
            unpack2(accp[i][jp], v0, v1);
            float av[2] = {v0, v1};
#pragma unroll
            for (int h = 0; h < 2; h++) {
                int j = jp * 2 + h;
                int cl = tx * 8 + j;
                float u  = xv[j] * ssg[cl];
                float v  = av[h] + sdtb[cl];
                float delta = fmaxf(v, 0.f) + __logf(1.f + __expf(-fabsf(v)));
                dl[j] = delta;
                du[j] = delta * u;
            }
        }
        float4* dst = (float4*)&g_dd[(size_t)r * DMODEL + c0];
#pragma unroll
        for (int j = 0; j < 4; j++) {
            float4 pk = make_float4(dl[2*j], du[2*j], dl[2*j+1], du[2*j+1]);
            dst[j] = pk;
            *(float4*)&sdd[lloc][tx * 8 + j * 2] = pk;
        }
    }
    __syncthreads();

    {
        const int dloc = tid & 127;
        const int nh   = tid >> 7;
        const int b    = row0 >> 11;
        const int chunk= (row0 >> 5) & (NCHUNK - 1);
        const int d    = by * 128 + dloc;
        const size_t base = (size_t)chunk * NCH + b * DMODEL + d;

        float A[8];
#pragma unroll
        for (int j = 0; j < 8; j++) A[j] = -__expf(A_log[(size_t)d * DSTATE + nh * 8 + j]);
        bool uniform = true;
#pragma unroll
        for (int j = 1; j < 8; j++) uniform &= (A[j] == A[0]);

        ull hp[4] = {0ull, 0ull, 0ull, 0ull};
        float T = 0.f;

        if (uniform) {
            const float A0 = A[0];
#pragma unroll 4
            for (int l = 0; l < CLEN; l++) {
                float2 t = sdd[l][dloc];
                T += t.x;
                float a = __expf(t.x * A0);
                ull ap  = pack2(a, a);
                ull dup = pack2(t.y, t.y);
                ulonglong2 b01 = *(const ulonglong2*)&Bs[l][nh * 8];
                ulonglong2 b23 = *(const ulonglong2*)&Bs[l][nh * 8 + 4];
                hp[0] = fma2(ap, hp[0], mul2(dup, b01.x));
                hp[1] = fma2(ap, hp[1], mul2(dup, b01.y));
                hp[2] = fma2(ap, hp[2], mul2(dup, b23.x));
                hp[3] = fma2(ap, hp[3], mul2(dup, b23.y));
            }
        } else {
#pragma unroll 2
            for (int l = 0; l < CLEN; l++) {
                float2 t = sdd[l][dloc];
                T += t.x;
                ull dup = pack2(t.y, t.y);
                ulonglong2 b01 = *(const ulonglong2*)&Bs[l][nh * 8];
                ulonglong2 b23 = *(const ulonglong2*)&Bs[l][nh * 8 + 4];
                ull bb[4] = {b01.x, b01.y, b23.x, b23.y};
#pragma unroll
                for (int p = 0; p < 4; p++) {
                    ull ap = pack2(__expf(t.x * A[p*2]), __expf(t.x * A[p*2+1]));
                    hp[p] = fma2(ap, hp[p], mul2(dup, bb[p]));
                }
            }
        }
#pragma unroll
        for (int p = 0; p < 4; p++)
            *(ull*)&g_hl[base * DSTATE + nh * 8 + p * 2] = hp[p];
        if (nh == 0) g_T[base] = T;
    }
}

// ---------------------------------------------------------------------------
// K3 (fused pass B + pass C with device-wide spin barrier).
// ---------------------------------------------------------------------------
__global__ __launch_bounds__(256, 4)
void scanBC_kernel(const float* __restrict__ A_log,
                   const float* __restrict__ Dp,
                   float* __restrict__ out)
{
    __shared__ __align__(16) float sm[CLEN * DSTATE * 2];

    const int tid  = threadIdx.x;
    const unsigned gen0 = *(volatile unsigned*)&g_barflag;

    {
        const int idx = blockIdx.x * 256 + tid;
        const int ch  = idx >> 6;
        const int q   = (idx >> 4) & 3;
        const int n   = idx & 15;
        const int d   = ch & (DMODEL - 1);

        const float A = -__expf(A_log[(size_t)d * DSTATE + n]);

        float a[16], hl[16];
#pragma unroll
        for (int i = 0; i < 16; i++) {
            int c = q * 16 + i;
            hl[i] = g_hl[((size_t)c * NCH + ch) * DSTATE + n];
            a[i]  = g_T [(size_t)c * NCH + ch];
        }
#pragma unroll
        for (int i = 0; i < 16; i++) a[i] = __expf(a[i] * A);

        float Aa = 1.f, Bb = 0.f;
#pragma unroll
        for (int i = 0; i < 16; i++) {
            Bb = fmaf(a[i], Bb, hl[i]);
            Aa *= a[i];
        }
        const int chl = tid >> 6;
        float2* smq = (float2*)sm;
        smq[(chl * 4 + q) * 16 + n] = make_float2(Aa, Bb);
        __syncthreads();

        float hin = 0.f;
#pragma unroll
        for (int qq = 0; qq < 3; qq++) {
            if (qq < q) {
                float2 m = smq[(chl * 4 + qq) * 16 + n];
                hin = fmaf(m.x, hin, m.y);
            }
        }
#pragma unroll
        for (int i = 0; i < 16; i++) {
            int c = q * 16 + i;
            g_hin[((size_t)c * NCH + ch) * DSTATE + n] = hin;
            hin = fmaf(a[i], hin, hl[i]);
        }
    }

    __threadfence();
    __syncthreads();
    if (tid == 0) {
        unsigned old = atomicAdd(&g_barcnt, 1u);
        if (old == gridDim.x - 1) {
            g_barcnt = 0;
            __threadfence();
            atomicAdd(&g_barflag, 1u);
        } else {
            while (*(volatile unsigned*)&g_barflag == gen0) { }
        }
    }
    __syncthreads();
    __threadfence();

    {
        float (*Bs)[DSTATE] = (float(*)[DSTATE])sm;
        float (*Cs)[DSTATE] = (float(*)[DSTATE])(sm + CLEN * DSTATE);

        const int blk   = blockIdx.x;
        const int b     = blk >> 8;
        const int rem   = blk & 255;
        const int dgrp  = rem >> 6;
        const int chunk = rem & 63;
        const int d     = dgrp * 256 + tid;
        const int ch    = b * DMODEL + d;
        const int l0    = chunk * CLEN;
        const size_t hbase = ((size_t)chunk * NCH + ch) * DSTATE;

        if (tid < CLEN * DSTATE / 4) {
            const float4* sb = (const float4*)&g_bp[((size_t)b * SEQLEN + l0) * DSTATE];
            ((float4*)Bs)[tid] = sb[tid];
        } else if (tid < CLEN * DSTATE / 2) {
            const float4* sc = (const float4*)&g_cp[((size_t)b * SEQLEN + l0) * DSTATE];
            ((float4*)Cs)[tid - CLEN * DSTATE / 4] = sc[tid - CLEN * DSTATE / 4];
        }

        float A[DSTATE];
#pragma unroll
        for (int n = 0; n < DSTATE; n++) A[n] = -__expf(A_log[(size_t)d * DSTATE + n]);
        bool uniform = true;
#pragma unroll
        for (int n = 1; n < DSTATE; n++) uniform &= (A[n] == A[0]);

        ull hp[8];
#pragma unroll
        for (int p = 0; p < 8; p++)
            hp[p] = *(const ull*)&g_hin[hbase + p * 2];

        const float Dpd = Dp[d];

        const float2* __restrict__ dd = g_dd + ((size_t)b * SEQLEN + l0) * DMODEL + d;
        float*        __restrict__ op = out  + ((size_t)b * SEQLEN + l0) * DMODEL + d;
        __syncthreads();

        if (uniform) {
            const float A0 = A[0];
            for (int lb = 0; lb < CLEN / 8; lb++) {
                float2 t[8];
#pragma unroll
                for (int i = 0; i < 8; i++) t[i] = dd[(size_t)(lb * 8 + i) * DMODEL];
                float av[8], u[8];
#pragma unroll
                for (int i = 0; i < 8; i++) {
                    av[i] = __expf(t[i].x * A0);
                    u[i]  = __fdividef(t[i].y, fmaxf(t[i].x, 1e-38f));
                }
#pragma unroll
                for (int i = 0; i < 8; i++) {
                    int l = lb * 8 + i;
                    ull ap  = pack2(av[i], av[i]);
                    ull dup = pack2(t[i].y, t[i].y);
                    ull yp  = 0ull;
                    const ulonglong2* bl = (const ulonglong2*)&Bs[l][0];
                    const ulonglong2* cl = (const ulonglong2*)&Cs[l][0];
#pragma unroll
                    for (int qd = 0; qd < 4; qd++) {
                        ulonglong2 bq = bl[qd];
                        ulonglong2 cq = cl[qd];
                        hp[2*qd+0] = fma2(ap, hp[2*qd+0], mul2(dup, bq.x));
                        yp         = fma2(hp[2*qd+0], cq.x, yp);
                        hp[2*qd+1] = fma2(ap, hp[2*qd+1], mul2(dup, bq.y));
                        yp         = fma2(hp[2*qd+1], cq.y, yp);
                    }
                    float ylo, yhi;
                    unpack2(yp, ylo, yhi);
                    op[(size_t)l * DMODEL] = fmaf(u[i], Dpd, ylo + yhi);
                }
            }
        } else {
            for (int lb = 0; lb < CLEN / 8; lb++) {
                float2 t[8];
#pragma unroll
                for (int i = 0; i < 8; i++) t[i] = dd[(size_t)(lb * 8 + i) * DMODEL];
                float u[8];
#pragma unroll
                for (int i = 0; i < 8; i++)
                    u[i] = __fdividef(t[i].y, fmaxf(t[i].x, 1e-38f));
#pragma unroll
                for (int i = 0; i < 8; i++) {
                    int l = lb * 8 + i;
                    ull dup = pack2(t[i].y, t[i].y);
                    ull yp  = 0ull;
                    const ulonglong2* bl = (const ulonglong2*)&Bs[l][0];
                    const ulonglong2* cl = (const ulonglong2*)&Cs[l][0];
#pragma unroll
                    for (int qd = 0; qd < 4; qd++) {
                        ulonglong2 bq = bl[qd];
                        ulonglong2 cq = cl[qd];
                        ull ap0 = pack2(__expf(t[i].x * A[4*qd+0]), __expf(t[i].x * A[4*qd+1]));
                        ull ap1 = pack2(__expf(t[i].x * A[4*qd+2]), __expf(t[i].x * A[4*qd+3]));
                        hp[2*qd+0] = fma2(ap0, hp[2*qd+0], mul2(dup, bq.x));
                        yp         = fma2(hp[2*qd+0], cq.x, yp);
                        hp[2*qd+1] = fma2(ap1, hp[2*qd+1], mul2(dup, bq.y));
                        yp         = fma2(hp[2*qd+1], cq.y, yp);
                    }
                    float ylo, yhi;
                    unpack2(yp, ylo, yhi);
                    op[(size_t)l * DMODEL] = fmaf(u[i], Dpd, ylo + yhi);
                }
            }
        }
    }
}

// ---------------------------------------------------------------------------
// Launch: 4 kernels
// ---------------------------------------------------------------------------
extern "C" void kernel_launch(void* const* d_in, const int* in_sizes, int n_in,
                              void* d_out, int out_size)
{
    const float* x    = (const float*)d_in[0];
    const float* Alog = (const float*)d_in[1];
    const float* xpw  = (const float*)d_in[2];
    const float* dtw  = (const float*)d_in[3];
    const float* dtb  = (const float*)d_in[4];
    const float* Dp   = (const float*)d_in[5];
    const float* te   = (const float*)d_in[6];
    float* out = (float*)d_out;

    prep_split_kernel<<<4096 + 96, 256>>>(x, xpw, te);
    gemm1_wmma_kernel<<<dim3(64, KSPLIT), 256>>>();
    gemm2s_kernel    <<<dim3(NROWS / 32, DMODEL / 128), 256>>>(x, dtw, dtb, te, Alog);
    scanBC_kernel    <<<SCAN_GRID, 256>>>(Alog, Dp, out);
}